// round 5
// baseline (speedup 1.0000x reference)
#include <cuda_runtime.h>
#include <cuda_bf16.h>

// Dequant: groups of 17 int32 (16 "byte" ints -> 32 nibbles, 1 scale int).
// out[g*32 + i] = (nibble_i - 8) / 12 * exp2(clamp(scale-127, -126, 127))
//
// Persistent grid-stride kernel, double-buffered smem staging with register
// prefetch: next tile's coalesced LDG.128s are in flight while the current
// tile is dequantized and stored (STG.128, warp-coalesced). One wave, no
// wave-transition DRAM bubbles.

#define THREADS 256
#define GROUPS_PER_TILE 256
#define INTS_PER_TILE  (GROUPS_PER_TILE * 17)           // 4352
#define INT4_PER_TILE  (INTS_PER_TILE / 4)              // 1088
#define QUADS_PER_TILE (GROUPS_PER_TILE * 8)            // 2048
#define LD_PER_THREAD 5                                 // ceil(1088/256)

__global__ void __launch_bounds__(THREADS) dequant_mxfp4_kernel(
    const int* __restrict__ packed,
    float4* __restrict__ out,
    int num_tiles)
{
    __shared__ int4 sm[2][INT4_PER_TILE];

    int tile = blockIdx.x;
    int stride = gridDim.x;

    // Prefetch first tile into registers
    int4 r[LD_PER_THREAD];
    {
        const int4* src = (const int4*)(packed + (size_t)tile * INTS_PER_TILE);
        #pragma unroll
        for (int i = 0; i < LD_PER_THREAD; i++) {
            int idx = threadIdx.x + i * THREADS;
            if (idx < INT4_PER_TILE) r[i] = __ldcs(src + idx);
        }
    }

    int buf = 0;
    while (tile < num_tiles) {
        // Commit prefetched tile to smem
        #pragma unroll
        for (int i = 0; i < LD_PER_THREAD; i++) {
            int idx = threadIdx.x + i * THREADS;
            if (idx < INT4_PER_TILE) sm[buf][idx] = r[i];
        }
        __syncthreads();

        // Kick off next tile's loads (in flight during compute below)
        int next = tile + stride;
        if (next < num_tiles) {
            const int4* src = (const int4*)(packed + (size_t)next * INTS_PER_TILE);
            #pragma unroll
            for (int i = 0; i < LD_PER_THREAD; i++) {
                int idx = threadIdx.x + i * THREADS;
                if (idx < INT4_PER_TILE) r[i] = __ldcs(src + idx);
            }
        }

        // Dequant current tile: 8 quads per thread, block-strided stores
        const int* smi = (const int*)sm[buf];
        float4* dst = out + (size_t)tile * QUADS_PER_TILE;
        #pragma unroll
        for (int j = 0; j < 8; j++) {
            int lq  = threadIdx.x + j * THREADS;   // 0..2047
            int lg  = lq >> 3;
            int sub = lq & 7;
            int base = lg * 17;

            int v0 = smi[base + sub * 2];
            int v1 = smi[base + sub * 2 + 1];
            int s  = smi[base + 16];

            // exp2(clip(s-127,-126,127)) == float with exponent clamp(s,1,254)
            int e = min(max(s, 1), 254);
            float scale = __int_as_float(e << 23) * (1.0f / 12.0f);

            float4 o;
            o.x = (float)((v0 & 15)        - 8) * scale;
            o.y = (float)(((v0 >> 4) & 15) - 8) * scale;
            o.z = (float)((v1 & 15)        - 8) * scale;
            o.w = (float)(((v1 >> 4) & 15) - 8) * scale;

            __stcs(dst + lq, o);
        }

        buf ^= 1;
        tile = next;
    }
}

extern "C" void kernel_launch(void* const* d_in, const int* in_sizes, int n_in,
                              void* d_out, int out_size)
{
    const int* packed = (const int*)d_in[0];
    float4* out = (float4*)d_out;

    int num_quads = out_size / 4;                        // 33,554,432
    int num_tiles = num_quads / QUADS_PER_TILE;          // 16384 (exact)

    int blocks = 148 * 8;                                // one wave, persistent
    dequant_mxfp4_kernel<<<blocks, THREADS>>>(packed, out, num_tiles);
}

// round 6
// speedup vs baseline: 1.0234x; 1.0234x over previous
#include <cuda_runtime.h>
#include <cuda_bf16.h>

// Dequant: groups of 17 int32 (16 "byte" ints -> 32 nibbles, 1 scale int).
// out[g*32 + i] = (nibble_i - 8) / 12 * exp2(clamp(scale-127, -126, 127))
//
// Block owns 256 groups (17408 B). Input staged via coalesced LDG.128 into
// smem PADDED to 20 ints/group so each thread's 4 data ints are one LDS.128.
// Each thread emits 8 consecutive floats with a single 256-bit store
// (st.global.v8.b32, sm_100a+), 4 per tile: half the store issues of STG.128.

#define THREADS 256
#define GROUPS_PER_BLOCK 256
#define INTS_PER_BLOCK  (GROUPS_PER_BLOCK * 17)   // 4352
#define INT4_PER_BLOCK  (INTS_PER_BLOCK / 4)      // 1088
#define PAD_STRIDE 20                             // 80 B per group, 16B-aligned
#define PAIRS_PER_BLOCK (GROUPS_PER_BLOCK * 4)    // 1024 float8s
#define FLOATS_PER_BLOCK (GROUPS_PER_BLOCK * 32)  // 8192

__device__ __forceinline__ void stg256_cs(float* p, const float f[8])
{
    asm volatile(
        "st.global.cs.v8.b32 [%0], {%1,%2,%3,%4,%5,%6,%7,%8};"
        :: "l"(p),
           "r"(__float_as_uint(f[0])), "r"(__float_as_uint(f[1])),
           "r"(__float_as_uint(f[2])), "r"(__float_as_uint(f[3])),
           "r"(__float_as_uint(f[4])), "r"(__float_as_uint(f[5])),
           "r"(__float_as_uint(f[6])), "r"(__float_as_uint(f[7]))
        : "memory");
}

__global__ void __launch_bounds__(THREADS) dequant_mxfp4_kernel(
    const int* __restrict__ packed,
    float* __restrict__ out)
{
    __shared__ int sm[GROUPS_PER_BLOCK * PAD_STRIDE];   // 20480 B

    // --- Stage: coalesced LDG.128, scatter into padded group layout ---
    const int4* src = (const int4*)(packed + (size_t)blockIdx.x * INTS_PER_BLOCK);
    #pragma unroll
    for (int i = 0; i < 5; i++) {
        int idx = threadIdx.x + i * THREADS;
        if (idx < INT4_PER_BLOCK) {
            int4 v = __ldcs(src + idx);
            int lin = idx * 4;                  // linear int index 0..4351
            #pragma unroll
            for (int k = 0; k < 4; k++) {
                int l = lin + k;
                int g = l / 17;                 // reciprocal-mul
                int r = l - g * 17;
                sm[g * PAD_STRIDE + r] = (&v.x)[k];
            }
        }
    }
    __syncthreads();

    // --- Dequant: 4 float8s per thread, block-strided 256-bit stores ---
    float* dst = out + (size_t)blockIdx.x * FLOATS_PER_BLOCK;

    #pragma unroll
    for (int j = 0; j < 4; j++) {
        int p  = threadIdx.x + j * THREADS;     // pair index 0..1023
        int lg = p >> 2;                        // local group
        int sp = p & 3;                         // which 4-int chunk (16 nibbles / 2... 8 floats)

        int4 v = *(const int4*)(sm + lg * PAD_STRIDE + sp * 4);
        int s  = sm[lg * PAD_STRIDE + 16];

        // exp2(clip(s-127,-126,127)) == float with exponent field clamp(s,1,254)
        int e = min(max(s, 1), 254);
        float scale = __int_as_float(e << 23) * (1.0f / 12.0f);

        float f[8];
        f[0] = (float)((v.x & 15)        - 8) * scale;
        f[1] = (float)(((v.x >> 4) & 15) - 8) * scale;
        f[2] = (float)((v.y & 15)        - 8) * scale;
        f[3] = (float)(((v.y >> 4) & 15) - 8) * scale;
        f[4] = (float)((v.z & 15)        - 8) * scale;
        f[5] = (float)(((v.z >> 4) & 15) - 8) * scale;
        f[6] = (float)((v.w & 15)        - 8) * scale;
        f[7] = (float)(((v.w >> 4) & 15) - 8) * scale;

        stg256_cs(dst + p * 8, f);
    }
}

extern "C" void kernel_launch(void* const* d_in, const int* in_sizes, int n_in,
                              void* d_out, int out_size)
{
    const int* packed = (const int*)d_in[0];
    float* out = (float*)d_out;

    int num_quads = out_size / 4;                          // 33,554,432
    int blocks = num_quads / (FLOATS_PER_BLOCK / 4);       // 16384 (exact)

    dequant_mxfp4_kernel<<<blocks, THREADS>>>(packed, out);
}

// round 7
// speedup vs baseline: 1.0276x; 1.0041x over previous
#include <cuda_runtime.h>
#include <cstdint>

// Dequant: groups of 17 int32 (16 "byte" ints -> 32 nibbles, 1 scale int).
// out[g*32 + i] = (nibble_i - 8) / 12 * exp2(clamp(scale-127, -126, 127))
//
// Input tile (17408 B = 256 groups) fetched by ONE cp.async.bulk (TMA bulk
// copy) per block into smem; SM does only LDS + warp-coalesced STG.128.

#define THREADS 256
#define GROUPS_PER_BLOCK 256
#define INTS_PER_BLOCK   (GROUPS_PER_BLOCK * 17)   // 4352
#define BYTES_PER_BLOCK  (INTS_PER_BLOCK * 4)      // 17408 (16B multiple)
#define QUADS_PER_BLOCK  (GROUPS_PER_BLOCK * 8)    // 2048

__device__ __forceinline__ uint32_t smem_u32(const void* p) {
    uint32_t a;
    asm("{ .reg .u64 t; cvta.to.shared.u64 t, %1; cvt.u32.u64 %0, t; }"
        : "=r"(a) : "l"(p));
    return a;
}

__global__ void __launch_bounds__(THREADS) dequant_mxfp4_kernel(
    const int* __restrict__ packed,
    float4* __restrict__ out)
{
    __shared__ alignas(16) int sm[INTS_PER_BLOCK];
    __shared__ alignas(8) uint64_t mbar;

    uint32_t sm_addr   = smem_u32(sm);
    uint32_t mbar_addr = smem_u32(&mbar);

    if (threadIdx.x == 0) {
        asm volatile("mbarrier.init.shared.b64 [%0], 1;" :: "r"(mbar_addr) : "memory");
    }
    __syncthreads();

    if (threadIdx.x == 0) {
        asm volatile("fence.proxy.async.shared::cta;" ::: "memory");
        asm volatile("mbarrier.arrive.expect_tx.shared.b64 _, [%0], %1;"
                     :: "r"(mbar_addr), "r"((uint32_t)BYTES_PER_BLOCK) : "memory");
        const char* src = (const char*)packed + (size_t)blockIdx.x * BYTES_PER_BLOCK;
        asm volatile(
            "cp.async.bulk.shared::cta.global.mbarrier::complete_tx::bytes "
            "[%0], [%1], %2, [%3];"
            :: "r"(sm_addr), "l"(src), "r"((uint32_t)BYTES_PER_BLOCK), "r"(mbar_addr)
            : "memory");
    }

    // All threads wait on the bulk-copy completion (phase 0, acquire).
    {
        uint32_t done;
        asm volatile(
            "{\n\t.reg .pred p;\n\t"
            "mbarrier.try_wait.parity.acquire.cta.shared::cta.b64 p, [%1], %2;\n\t"
            "selp.b32 %0, 1, 0, p;\n\t}"
            : "=r"(done) : "r"(mbar_addr), "r"(0u) : "memory");
        if (!done) {
            asm volatile(
                "{\n\t.reg .pred P1;\n"
                "WAIT_LOOP_%=:\n\t"
                "mbarrier.try_wait.parity.acquire.cta.shared::cta.b64 P1, [%0], %1, 0x989680;\n\t"
                "@P1 bra.uni WAIT_DONE_%=;\n\t"
                "bra.uni WAIT_LOOP_%=;\n"
                "WAIT_DONE_%=:\n\t}"
                :: "r"(mbar_addr), "r"(0u) : "memory");
        }
    }

    // --- Dequant: 8 quads per thread, block-strided coalesced STG.128 ---
    float4* dst = out + (size_t)blockIdx.x * QUADS_PER_BLOCK;

    #pragma unroll
    for (int j = 0; j < 8; j++) {
        int lq  = threadIdx.x + j * THREADS;   // local quad 0..2047
        int lg  = lq >> 3;                     // local group
        int sub = lq & 7;
        int base = lg * 17;

        int v0 = sm[base + sub * 2];
        int v1 = sm[base + sub * 2 + 1];
        int s  = sm[base + 16];

        // exp2(clip(s-127,-126,127)) == float with exponent field clamp(s,1,254)
        int e = min(max(s, 1), 254);
        float scale = __int_as_float(e << 23) * (1.0f / 12.0f);

        float4 r;
        r.x = (float)((v0 & 15)        - 8) * scale;
        r.y = (float)(((v0 >> 4) & 15) - 8) * scale;
        r.z = (float)((v1 & 15)        - 8) * scale;
        r.w = (float)(((v1 >> 4) & 15) - 8) * scale;

        __stcs(dst + lq, r);
    }
}

extern "C" void kernel_launch(void* const* d_in, const int* in_sizes, int n_in,
                              void* d_out, int out_size)
{
    const int* packed = (const int*)d_in[0];
    float4* out = (float4*)d_out;

    int num_quads = out_size / 4;                    // 33,554,432
    int blocks = num_quads / QUADS_PER_BLOCK;        // 16384 (exact)

    dequant_mxfp4_kernel<<<blocks, THREADS>>>(packed, out);
}

// round 8
// speedup vs baseline: 1.0501x; 1.0219x over previous
#include <cuda_runtime.h>
#include <cstdint>

// Dequant: groups of 17 int32 (16 "byte" ints -> 32 nibbles, 1 scale int).
// out[g*32 + i] = (nibble_i - 8) / 12 * exp2(clamp(scale-127, -126, 127))
//
// Fully engine-driven: TMA bulk load (8704 B) -> smem, SM dequants into an
// output smem tile (16384 B), one TMA bulk store per block. Write stream
// becomes 16 KB contiguous bursts instead of interleaved 512 B STG bursts.

#define THREADS 256
#define GROUPS_PER_BLOCK 128
#define INTS_PER_BLOCK   (GROUPS_PER_BLOCK * 17)   // 2176
#define IN_BYTES         (INTS_PER_BLOCK * 4)      // 8704 (16B multiple)
#define QUADS_PER_BLOCK  (GROUPS_PER_BLOCK * 8)    // 1024
#define OUT_BYTES        (QUADS_PER_BLOCK * 16)    // 16384

__device__ __forceinline__ uint32_t smem_u32(const void* p) {
    uint32_t a;
    asm("{ .reg .u64 t; cvta.to.shared.u64 t, %1; cvt.u32.u64 %0, t; }"
        : "=r"(a) : "l"(p));
    return a;
}

__global__ void __launch_bounds__(THREADS) dequant_mxfp4_kernel(
    const int* __restrict__ packed,
    float4* __restrict__ out)
{
    __shared__ alignas(16) int    sm_in[INTS_PER_BLOCK];
    __shared__ alignas(16) float4 sm_out[QUADS_PER_BLOCK];
    __shared__ alignas(8) uint64_t mbar;

    uint32_t in_addr   = smem_u32(sm_in);
    uint32_t out_addr  = smem_u32(sm_out);
    uint32_t mbar_addr = smem_u32(&mbar);

    if (threadIdx.x == 0) {
        asm volatile("mbarrier.init.shared.b64 [%0], 1;" :: "r"(mbar_addr) : "memory");
    }
    __syncthreads();

    if (threadIdx.x == 0) {
        asm volatile("fence.proxy.async.shared::cta;" ::: "memory");
        asm volatile("mbarrier.arrive.expect_tx.shared.b64 _, [%0], %1;"
                     :: "r"(mbar_addr), "r"((uint32_t)IN_BYTES) : "memory");
        const char* src = (const char*)packed + (size_t)blockIdx.x * IN_BYTES;
        asm volatile(
            "cp.async.bulk.shared::cta.global.mbarrier::complete_tx::bytes "
            "[%0], [%1], %2, [%3];"
            :: "r"(in_addr), "l"(src), "r"((uint32_t)IN_BYTES), "r"(mbar_addr)
            : "memory");
    }

    // Wait for bulk load (phase 0, acquire)
    {
        uint32_t done;
        asm volatile(
            "{\n\t.reg .pred p;\n\t"
            "mbarrier.try_wait.parity.acquire.cta.shared::cta.b64 p, [%1], %2;\n\t"
            "selp.b32 %0, 1, 0, p;\n\t}"
            : "=r"(done) : "r"(mbar_addr), "r"(0u) : "memory");
        if (!done) {
            asm volatile(
                "{\n\t.reg .pred P1;\n"
                "WAIT_LOOP_%=:\n\t"
                "mbarrier.try_wait.parity.acquire.cta.shared::cta.b64 P1, [%0], %1, 0x989680;\n\t"
                "@P1 bra.uni WAIT_DONE_%=;\n\t"
                "bra.uni WAIT_LOOP_%=;\n"
                "WAIT_DONE_%=:\n\t}"
                :: "r"(mbar_addr), "r"(0u) : "memory");
        }
    }

    // --- Dequant into smem output tile: 4 quads per thread ---
    #pragma unroll
    for (int j = 0; j < 4; j++) {
        int lq  = threadIdx.x + j * THREADS;   // 0..1023
        int lg  = lq >> 3;
        int sub = lq & 7;
        int base = lg * 17;

        int v0 = sm_in[base + sub * 2];
        int v1 = sm_in[base + sub * 2 + 1];
        int s  = sm_in[base + 16];

        // exp2(clip(s-127,-126,127)) == float with exponent field clamp(s,1,254)
        int e = min(max(s, 1), 254);
        float scale = __int_as_float(e << 23) * (1.0f / 12.0f);

        float4 r;
        r.x = (float)((v0 & 15)        - 8) * scale;
        r.y = (float)(((v0 >> 4) & 15) - 8) * scale;
        r.z = (float)((v1 & 15)        - 8) * scale;
        r.w = (float)(((v1 >> 4) & 15) - 8) * scale;

        sm_out[lq] = r;
    }
    __syncthreads();

    // --- One bulk store: 16 KB contiguous write burst ---
    if (threadIdx.x == 0) {
        asm volatile("fence.proxy.async.shared::cta;" ::: "memory");
        char* dst = (char*)out + (size_t)blockIdx.x * OUT_BYTES;
        asm volatile(
            "cp.async.bulk.global.shared::cta.bulk_group [%0], [%1], %2;"
            :: "l"(dst), "r"(out_addr), "r"((uint32_t)OUT_BYTES)
            : "memory");
        asm volatile("cp.async.bulk.commit_group;" ::: "memory");
        asm volatile("cp.async.bulk.wait_group.read 0;" ::: "memory");
    }
}

extern "C" void kernel_launch(void* const* d_in, const int* in_sizes, int n_in,
                              void* d_out, int out_size)
{
    const int* packed = (const int*)d_in[0];
    float4* out = (float4*)d_out;

    int num_quads = out_size / 4;                    // 33,554,432
    int blocks = num_quads / QUADS_PER_BLOCK;        // 32768 (exact)

    dequant_mxfp4_kernel<<<blocks, THREADS>>>(packed, out);
}